// round 3
// baseline (speedup 1.0000x reference)
#include <cuda_runtime.h>
#include <cuda_fp16.h>

#define BB 64
#define TE 1024
#define TO 1000
#define AD 256
#define ED 256
#define HD 256
#define NM 80
#define NCTA 148

// ---------------- static device scratch ----------------
__device__ __half g_attn_h[BB*TE*AD];     // 32 MB : fp16 enc projection
__device__ __half g_enc_h [BB*TE*ED];     // 32 MB : fp16 enc_outputs
__device__ float  g_pre2  [TO*BB*HD];     // 62.5MB: prenet(all steps)
__device__ float  g_q     [BB*AD];
__device__ float  g_h     [2][BB*HD];
__device__ float  g_c     [BB*HD];
__device__ float  g_ctxp  [128*ED];       // per (b,half) ctx partials
__device__ float  g_sump  [128];
__device__ float  g_gates [4*BB*HD];      // [gt][b][j]
__device__ volatile unsigned g_arrive;

__device__ __forceinline__ float tanha(float x){
    float y; asm("tanh.approx.f32 %0, %1;" : "=f"(y) : "f"(x)); return y;
}
__device__ __forceinline__ float tanh_acc(float x){
    x = fminf(fmaxf(x, -15.f), 15.f);
    float e = __expf(2.f*x);
    return __fdividef(e - 1.f, e + 1.f);
}
__device__ __forceinline__ float sigm(float x){
    return __fdividef(1.f, 1.f + __expf(-x));
}

// ---------------- prologue 1: enc projection (fp16) + enc fp16 copy ----------------
__global__ void __launch_bounds__(256) k_prep_enc(const float* __restrict__ enc,
                                                  const float* __restrict__ Wenc,
                                                  const float* __restrict__ benc){
    __shared__ float4 enc_s[16][64];
    int tid = threadIdx.x;
    int b  = blockIdx.y;
    int t0 = blockIdx.x * 16;
    int base = (b*TE + t0)*ED;
    const float4* ev = (const float4*)(enc + base);
    for (int idx = tid; idx < 16*64; idx += 256) enc_s[idx>>6][idx&63] = ev[idx];
    for (int idx = tid; idx < 16*ED; idx += 256) g_enc_h[base+idx] = __float2half(enc[base+idx]);
    __syncthreads();
    float acc[16];
    #pragma unroll
    for (int i=0;i<16;i++) acc[i]=0.f;
    const float4* wv = (const float4*)Wenc + tid*64;
    for (int e=0;e<64;e++){
        float4 w = wv[e];
        #pragma unroll
        for (int i=0;i<16;i++){
            float4 x = enc_s[i][e];
            acc[i] += w.x*x.x + w.y*x.y + w.z*x.z + w.w*x.w;
        }
    }
    float bv = benc[tid];
    #pragma unroll
    for (int i=0;i<16;i++) g_attn_h[(b*TE + t0 + i)*AD + tid] = __float2half(acc[i] + bv);
}

// ---------------- prologue 2: prenet for all steps ----------------
#define TT 25
__global__ void __launch_bounds__(256) k_prenet(const float* __restrict__ tm,
                                                const float* __restrict__ W1, const float* __restrict__ b1,
                                                const float* __restrict__ W2, const float* __restrict__ b2){
    __shared__ float prev_s[TT][80];
    __shared__ float pre1_s[TT][256];
    int tid = threadIdx.x;
    int b  = blockIdx.y;
    int t0 = blockIdx.x * TT;
    for (int idx = tid; idx < TT*80; idx += 256){
        int tt = idx/80, m = idx%80;
        int t = t0 + tt;
        prev_s[tt][m] = (t==0) ? 0.f : tm[(b*TO + (t-1))*NM + m];
    }
    __syncthreads();
    float acc[TT];
    #pragma unroll
    for (int i=0;i<TT;i++) acc[i]=0.f;
    {
        const float4* w1v = (const float4*)W1 + tid*20;
        for (int m=0;m<20;m++){
            float4 w = w1v[m];
            #pragma unroll
            for (int i=0;i<TT;i++){
                float4 x = ((const float4*)prev_s[i])[m];
                acc[i] += w.x*x.x + w.y*x.y + w.z*x.z + w.w*x.w;
            }
        }
    }
    float bv1 = b1[tid];
    #pragma unroll
    for (int i=0;i<TT;i++) pre1_s[i][tid] = fmaxf(acc[i] + bv1, 0.f);
    __syncthreads();
    #pragma unroll
    for (int i=0;i<TT;i++) acc[i]=0.f;
    {
        const float4* w2v = (const float4*)W2 + tid*64;
        for (int m=0;m<64;m++){
            float4 w = w2v[m];
            #pragma unroll
            for (int i=0;i<TT;i++){
                float4 x = ((const float4*)pre1_s[i])[m];
                acc[i] += w.x*x.x + w.y*x.y + w.z*x.z + w.w*x.w;
            }
        }
    }
    float bv2 = b2[tid];
    #pragma unroll
    for (int i=0;i<TT;i++) g_pre2[(t0+i)*(BB*HD) + b*HD + tid] = fmaxf(acc[i] + bv2, 0.f);
}

// ---------------- prologue 3: init state + barrier counter ----------------
__global__ void k_init(const float* __restrict__ bdec){
    int b = blockIdx.x, tid = threadIdx.x;
    g_h[0][b*HD+tid] = 0.f;
    g_c[b*HD+tid]    = 0.f;
    g_q[b*AD+tid]    = bdec[tid];     // h=0 -> q = b_dec
    if (b==0 && tid==0) g_arrive = 0u;
}

// ---------------- grid barrier ----------------
__device__ __forceinline__ void gsync(unsigned &gen){
    __threadfence();
    __syncthreads();
    if (threadIdx.x == 0){
        atomicAdd((unsigned*)&g_arrive, 1u);
        gen += NCTA;
        while (g_arrive < gen) { }
    }
    __syncthreads();
}

// ---------------- persistent main kernel ----------------
struct SA { float q[256]; float v[256]; float wctx[8][256]; float wsum[8]; };
struct SB { float x[16][772]; float rs[16]; };
struct SC { float comb[512]; };
union  SU { SA a; SB b; SC c; };

__global__ void __launch_bounds__(256,1) k_main(
        const float* __restrict__ mask, const float* __restrict__ vw, const float* __restrict__ vb,
        const float* __restrict__ Wih,  const float* __restrict__ Whh,
        const float* __restrict__ bih,  const float* __restrict__ bhh,
        const float* __restrict__ Wdec, const float* __restrict__ bdec,
        const float* __restrict__ melW, const float* __restrict__ melb,
        const float* __restrict__ stopW,const float* __restrict__ stopb,
        float* __restrict__ out){
    __shared__ SU sm;
    const int c   = blockIdx.x;
    const int tid = threadIdx.x;
    const int l   = tid & 31, w = tid >> 5;
    unsigned gen = 0;
    const float vb0 = vb[0];

    for (int t = 0; t < TO; t++){
        // ================= Phase A : attention (CTAs 0..127) =================
        if (c < 128){
            const int b = c >> 1, half = c & 1;
            sm.a.q[tid] = __ldcg(&g_q[b*AD + tid]);
            sm.a.v[tid] = vw[tid];
            __syncthreads();
            const float2* q2 = (const float2*)sm.a.q;
            const float2* v2 = (const float2*)sm.a.v;
            float acc[8];
            #pragma unroll
            for (int k=0;k<8;k++) acc[k]=0.f;
            float esum = 0.f;
            const int tbase = half*512 + w*64;
            const __half2* ah = (const __half2*)g_attn_h;
            const __half2* eh = (const __half2*)g_enc_h;
            for (int i=0;i<64;i++){
                int tt = tbase + i;
                if (mask[b*TE + tt] != 0.f){
                    size_t roff = ((size_t)(b*TE + tt))*128;
                    float p = 0.f;
                    float2 ef[4];
                    #pragma unroll
                    for (int k=0;k<4;k++){
                        int ii = l + 32*k;
                        float2 f = __half22float2(__ldcg(&ah[roff + ii]));
                        float2 qv = q2[ii];
                        float ta = tanha(f.x + qv.x);
                        float tb = tanha(f.y + qv.y);
                        float2 vv = v2[ii];
                        p = fmaf(vv.x, ta, p);
                        p = fmaf(vv.y, tb, p);
                        ef[k] = __half22float2(__ldcg(&eh[roff + ii]));
                    }
                    #pragma unroll
                    for (int off=16; off; off>>=1) p += __shfl_xor_sync(0xffffffffu, p, off);
                    float e = __expf(p + vb0);
                    esum += e;
                    #pragma unroll
                    for (int k=0;k<4;k++){
                        acc[2*k]   = fmaf(e, ef[k].x, acc[2*k]);
                        acc[2*k+1] = fmaf(e, ef[k].y, acc[2*k+1]);
                    }
                }
            }
            #pragma unroll
            for (int k=0;k<4;k++){
                int ii = l + 32*k;
                sm.a.wctx[w][2*ii]   = acc[2*k];
                sm.a.wctx[w][2*ii+1] = acc[2*k+1];
            }
            if (l==0) sm.a.wsum[w] = esum;
            __syncthreads();
            float s = 0.f;
            #pragma unroll
            for (int ww=0;ww<8;ww++) s += sm.a.wctx[ww][tid];
            g_ctxp[c*ED + tid] = s;
            if (tid==0){
                float ss = 0.f;
                #pragma unroll
                for (int ww=0;ww<8;ww++) ss += sm.a.wsum[ww];
                g_sump[c] = ss;
            }
        }
        gsync(gen);

        // ================= Phase B : gate GEMM (CTAs 0..127) =================
        if (c < 128){
            const int rb = c >> 2, cb = c & 3;
            const int b0 = cb*16;
            if (tid < 16){
                float ssum = __ldcg(&g_sump[2*(b0+tid)]) + __ldcg(&g_sump[2*(b0+tid)+1]);
                sm.b.rs[tid] = __fdividef(1.f, ssum);
            }
            __syncthreads();
            const int ph = t & 1;
            for (int idx = tid; idx < 16*768; idx += 256){
                int bb = idx/768, k = idx - bb*768;
                int b = b0 + bb;
                float v;
                if (k < 256)      v = g_pre2[(size_t)t*(BB*HD) + b*HD + k];
                else if (k < 512) v = (__ldcg(&g_ctxp[(2*b)*ED + (k-256)]) +
                                       __ldcg(&g_ctxp[(2*b+1)*ED + (k-256)])) * sm.b.rs[bb];
                else              v = __ldcg(&g_h[ph][b*HD + (k-512)]);
                sm.b.x[bb][k] = v;
            }
            __syncthreads();
            const int rr = tid >> 3, bp = tid & 7;
            const int r = rb*32 + rr;
            float acc1 = bih[r] + bhh[r];
            float acc2 = acc1;
            const float4* wih = (const float4*)Wih + r*128;
            const float4* whh = (const float4*)Whh + r*64;
            const float4* x1  = (const float4*)sm.b.x[bp];
            const float4* x2  = (const float4*)sm.b.x[bp+8];
            #pragma unroll 4
            for (int k=0;k<128;k++){
                float4 ww = wih[k], a = x1[k], bq = x2[k];
                acc1 += ww.x*a.x + ww.y*a.y + ww.z*a.z + ww.w*a.w;
                acc2 += ww.x*bq.x + ww.y*bq.y + ww.z*bq.z + ww.w*bq.w;
            }
            #pragma unroll 4
            for (int k=0;k<64;k++){
                float4 ww = whh[k], a = x1[128+k], bq = x2[128+k];
                acc1 += ww.x*a.x + ww.y*a.y + ww.z*a.z + ww.w*a.w;
                acc2 += ww.x*bq.x + ww.y*bq.y + ww.z*bq.z + ww.w*bq.w;
            }
            const int gt = r >> 8, j = r & 255;
            g_gates[gt*(BB*HD) + (b0+bp)*HD + j]   = acc1;
            g_gates[gt*(BB*HD) + (b0+bp+8)*HD + j] = acc2;
        }
        gsync(gen);

        // ====== Phase C : LSTM cell + heads + next query (CTAs 0..63) ======
        if (c < 64){
            const int b = c;
            const int j = tid;
            const int ph1 = (t+1) & 1;
            float ssum = __ldcg(&g_sump[2*b]) + __ldcg(&g_sump[2*b+1]);
            float rsum = __fdividef(1.f, ssum);
            float gi = __ldcg(&g_gates[0*(BB*HD) + b*HD + j]);
            float gf = __ldcg(&g_gates[1*(BB*HD) + b*HD + j]);
            float gg = __ldcg(&g_gates[2*(BB*HD) + b*HD + j]);
            float go = __ldcg(&g_gates[3*(BB*HD) + b*HD + j]);
            float cold = g_c[b*HD + j];
            float cn = sigm(gf)*cold + sigm(gi)*tanh_acc(gg);
            float hn = sigm(go)*tanh_acc(cn);
            g_c[b*HD + j] = cn;
            g_h[ph1][b*HD + j] = hn;
            float ctxn = (__ldcg(&g_ctxp[(2*b)*ED + j]) + __ldcg(&g_ctxp[(2*b+1)*ED + j])) * rsum;
            sm.c.comb[j]       = hn;
            sm.c.comb[256 + j] = ctxn;
            __syncthreads();
            const float4* cv = (const float4*)sm.c.comb;
            if (tid < 80){
                float acc = melb[tid];
                const float4* wv = (const float4*)melW + tid*128;
                #pragma unroll 4
                for (int k=0;k<128;k++){ float4 ww=wv[k], x=cv[k]; acc += ww.x*x.x+ww.y*x.y+ww.z*x.z+ww.w*x.w; }
                out[(b*TO + t)*NM + tid] = acc;
            } else if (tid == 80){
                float acc = stopb[0];
                const float4* wv = (const float4*)stopW;
                for (int k=0;k<128;k++){ float4 ww=wv[k], x=cv[k]; acc += ww.x*x.x+ww.y*x.y+ww.z*x.z+ww.w*x.w; }
                out[BB*TO*NM + b*TO + t] = acc;
            }
            {
                float acc = bdec[tid];
                const float4* wv = (const float4*)Wdec + tid*64;
                #pragma unroll 4
                for (int k=0;k<64;k++){ float4 ww=wv[k], x=cv[k]; acc += ww.x*x.x+ww.y*x.y+ww.z*x.z+ww.w*x.w; }
                g_q[b*AD + tid] = acc;
            }
        }
        gsync(gen);
    }
}

// ---------------- launch ----------------
extern "C" void kernel_launch(void* const* d_in, const int* in_sizes, int n_in,
                              void* d_out, int out_size){
    (void)in_sizes; (void)n_in; (void)out_size;
    const float* enc  = (const float*)d_in[0];
    const float* tm   = (const float*)d_in[1];
    const float* Wenc = (const float*)d_in[2];
    const float* benc = (const float*)d_in[3];
    const float* Wdec = (const float*)d_in[4];
    const float* bdec = (const float*)d_in[5];
    const float* vw   = (const float*)d_in[6];
    const float* vb   = (const float*)d_in[7];
    const float* W1   = (const float*)d_in[8];
    const float* b1   = (const float*)d_in[9];
    const float* W2   = (const float*)d_in[10];
    const float* b2   = (const float*)d_in[11];
    const float* Wih  = (const float*)d_in[12];
    const float* Whh  = (const float*)d_in[13];
    const float* bih  = (const float*)d_in[14];
    const float* bhh  = (const float*)d_in[15];
    const float* melW = (const float*)d_in[16];
    const float* melb = (const float*)d_in[17];
    const float* stopW= (const float*)d_in[18];
    const float* stopb= (const float*)d_in[19];
    const float* mask = (const float*)d_in[20];
    float* out = (float*)d_out;

    k_prep_enc<<<dim3(64,64),256>>>(enc, Wenc, benc);
    k_prenet  <<<dim3(40,64),256>>>(tm, W1, b1, W2, b2);
    k_init    <<<64,256>>>(bdec);
    k_main    <<<NCTA,256>>>(mask, vw, vb, Wih, Whh, bih, bhh, Wdec, bdec,
                             melW, melb, stopW, stopb, out);
}

// round 4
// speedup vs baseline: 1.3447x; 1.3447x over previous
#include <cuda_runtime.h>
#include <cuda_fp16.h>

#define BB 64
#define TE 1024
#define TO 1000
#define AD 256
#define ED 256
#define HD 256
#define NM 80
#define NCTA 296

// ---------------- static device scratch ----------------
__device__ __half g_attn_t[BB*AD*TE];     // 32 MB : fp16 enc projection, TRANSPOSED [b][a][t]
__device__ __half g_enc_h [BB*TE*ED];     // 32 MB : fp16 enc_outputs [b][t][d]
__device__ float  g_pre2  [TO*BB*HD];     // 62.5MB: prenet(all steps)
__device__ float  g_q     [BB*AD];
__device__ float  g_h     [2][BB*HD];
__device__ float  g_c     [BB*HD];
__device__ float  g_ctxp  [256*ED];       // per (b, t-quarter) ctx partials
__device__ float  g_sump  [256];
__device__ float  g_gates [4*BB*HD];      // [gt][b][j]
__device__ volatile unsigned g_arrive;

__device__ __forceinline__ float tanh_acc(float x){
    x = fminf(fmaxf(x, -15.f), 15.f);
    float e = __expf(2.f*x);
    return __fdividef(e - 1.f, e + 1.f);
}
__device__ __forceinline__ float sigm(float x){
    return __fdividef(1.f, 1.f + __expf(-x));
}

// ---------------- prologue 1: enc projection (fp16, transposed) + enc fp16 copy ----
__global__ void __launch_bounds__(256) k_prep_enc(const float* __restrict__ enc,
                                                  const float* __restrict__ Wenc,
                                                  const float* __restrict__ benc){
    __shared__ float4 enc_s[16][64];
    int tid = threadIdx.x;
    int b  = blockIdx.y;
    int t0 = blockIdx.x * 16;
    int base = (b*TE + t0)*ED;
    const float4* ev = (const float4*)(enc + base);
    for (int idx = tid; idx < 16*64; idx += 256) enc_s[idx>>6][idx&63] = ev[idx];
    for (int idx = tid; idx < 16*ED; idx += 256) g_enc_h[base+idx] = __float2half(enc[base+idx]);
    __syncthreads();
    float acc[16];
    #pragma unroll
    for (int i=0;i<16;i++) acc[i]=0.f;
    const float4* wv = (const float4*)Wenc + tid*64;
    for (int e=0;e<64;e++){
        float4 w = wv[e];
        #pragma unroll
        for (int i=0;i<16;i++){
            float4 x = enc_s[i][e];
            acc[i] += w.x*x.x + w.y*x.y + w.z*x.z + w.w*x.w;
        }
    }
    float bv = benc[tid];
    #pragma unroll
    for (int i=0;i<16;i++)
        g_attn_t[((size_t)(b*AD + tid))*TE + t0 + i] = __float2half(acc[i] + bv);
}

// ---------------- prologue 2: prenet for all steps ----------------
#define TT 25
__global__ void __launch_bounds__(256) k_prenet(const float* __restrict__ tm,
                                                const float* __restrict__ W1, const float* __restrict__ b1,
                                                const float* __restrict__ W2, const float* __restrict__ b2){
    __shared__ float prev_s[TT][80];
    __shared__ float pre1_s[TT][256];
    int tid = threadIdx.x;
    int b  = blockIdx.y;
    int t0 = blockIdx.x * TT;
    for (int idx = tid; idx < TT*80; idx += 256){
        int tt = idx/80, m = idx%80;
        int t = t0 + tt;
        prev_s[tt][m] = (t==0) ? 0.f : tm[(b*TO + (t-1))*NM + m];
    }
    __syncthreads();
    float acc[TT];
    #pragma unroll
    for (int i=0;i<TT;i++) acc[i]=0.f;
    {
        const float4* w1v = (const float4*)W1 + tid*20;
        for (int m=0;m<20;m++){
            float4 w = w1v[m];
            #pragma unroll
            for (int i=0;i<TT;i++){
                float4 x = ((const float4*)prev_s[i])[m];
                acc[i] += w.x*x.x + w.y*x.y + w.z*x.z + w.w*x.w;
            }
        }
    }
    float bv1 = b1[tid];
    #pragma unroll
    for (int i=0;i<TT;i++) pre1_s[i][tid] = fmaxf(acc[i] + bv1, 0.f);
    __syncthreads();
    #pragma unroll
    for (int i=0;i<TT;i++) acc[i]=0.f;
    {
        const float4* w2v = (const float4*)W2 + tid*64;
        for (int m=0;m<64;m++){
            float4 w = w2v[m];
            #pragma unroll
            for (int i=0;i<TT;i++){
                float4 x = ((const float4*)pre1_s[i])[m];
                acc[i] += w.x*x.x + w.y*x.y + w.z*x.z + w.w*x.w;
            }
        }
    }
    float bv2 = b2[tid];
    #pragma unroll
    for (int i=0;i<TT;i++) g_pre2[(size_t)(t0+i)*(BB*HD) + b*HD + tid] = fmaxf(acc[i] + bv2, 0.f);
}

// ---------------- prologue 3: init state + barrier counter ----------------
__global__ void k_init(const float* __restrict__ bdec){
    int b = blockIdx.x, tid = threadIdx.x;
    g_h[0][b*HD+tid] = 0.f;
    g_c[b*HD+tid]    = 0.f;
    g_q[b*AD+tid]    = bdec[tid];     // h=0 -> q = b_dec
    if (b==0 && tid==0) g_arrive = 0u;
}

// ---------------- grid barrier ----------------
__device__ __forceinline__ void gsync(unsigned &gen){
    __threadfence();
    __syncthreads();
    if (threadIdx.x == 0){
        atomicAdd((unsigned*)&g_arrive, 1u);
        gen += NCTA;
        while (g_arrive < gen) { }
    }
    __syncthreads();
}

// ---------------- persistent main kernel ----------------
struct SA { __half2 qh2[256]; float v[256]; float ep[8][64]; float es[256]; float wctx[8][256]; };
struct SB { float x[8][772]; float rs[8]; };
struct SC { float comb[512]; };
union  SU { SA a; SB b; SC c; };

__global__ void __launch_bounds__(256,2) k_main(
        const float* __restrict__ mask, const float* __restrict__ vw, const float* __restrict__ vb,
        const float* __restrict__ Wih,  const float* __restrict__ Whh,
        const float* __restrict__ bih,  const float* __restrict__ bhh,
        const float* __restrict__ Wdec, const float* __restrict__ bdec,
        const float* __restrict__ melW, const float* __restrict__ melb,
        const float* __restrict__ stopW,const float* __restrict__ stopb,
        float* __restrict__ out){
    __shared__ SU sm;
    const int c   = blockIdx.x;
    const int tid = threadIdx.x;
    const int l   = tid & 31, w = tid >> 5;
    unsigned gen = 0;
    const float vb0 = vb[0];

    for (int t = 0; t < TO; t++){
        // ======== Phase A : attention (CTAs 0..255 : b = c>>2, quarter = c&3) ========
        if (c < 256){
            const int b = c >> 2, qt = c & 3;
            sm.a.qh2[tid] = __half2half2(__float2half(__ldcg(&g_q[b*AD + tid])));
            sm.a.v[tid]   = vw[tid];
            __syncthreads();
            // --- energy: warp w -> t-quarter (w&3)*64..+64, a-half (w>>2)*128..+128
            const int wq = w & 3;
            const int a0 = (w >> 2) * 128;
            float2 acc = make_float2(0.f, 0.f);
            {
                size_t base2 = ((((size_t)(b*AD + a0))*TE) + qt*256 + wq*64) >> 1;
                const __half2* p = ((const __half2*)g_attn_t) + base2 + l;
                #pragma unroll 4
                for (int a = 0; a < 128; a++){
                    __half2 xv = __hadd2(__ldcg(p), sm.a.qh2[a0 + a]);
                    unsigned xi = *(unsigned*)&xv, ti;
                    asm("tanh.approx.f16x2 %0, %1;" : "=r"(ti) : "r"(xi));
                    __half2 th = *(__half2*)&ti;
                    float2 tf = __half22float2(th);
                    float vv = sm.a.v[a0 + a];
                    acc.x = fmaf(vv, tf.x, acc.x);
                    acc.y = fmaf(vv, tf.y, acc.y);
                    p += TE/2;
                }
            }
            sm.a.ep[w][2*l]   = acc.x;
            sm.a.ep[w][2*l+1] = acc.y;
            __syncthreads();
            {
                int tl = tid;
                int qd = tl >> 6, off = tl & 63;
                float e = sm.a.ep[qd][off] + sm.a.ep[qd+4][off];
                float mk = mask[b*TE + qt*256 + tl];
                sm.a.es[tl] = (mk != 0.f) ? __expf(e + vb0) : 0.f;
            }
            __syncthreads();
            // --- context partials over this quarter's 256 t
            float2 ca[4];
            #pragma unroll
            for (int k=0;k<4;k++) ca[k] = make_float2(0.f, 0.f);
            {
                size_t base2 = (((size_t)(b*TE + qt*256 + w*32))*ED) >> 1;
                const __half2* p = ((const __half2*)g_enc_h) + base2 + l;
                for (int i=0;i<32;i++){
                    float e = sm.a.es[w*32 + i];
                    if (e != 0.f){                       // warp-uniform
                        #pragma unroll
                        for (int k=0;k<4;k++){
                            float2 f = __half22float2(__ldcg(p + k*32));
                            ca[k].x = fmaf(e, f.x, ca[k].x);
                            ca[k].y = fmaf(e, f.y, ca[k].y);
                        }
                    }
                    p += ED/2;
                }
            }
            #pragma unroll
            for (int k=0;k<4;k++){
                sm.a.wctx[w][2*(l+32*k)]   = ca[k].x;
                sm.a.wctx[w][2*(l+32*k)+1] = ca[k].y;
            }
            __syncthreads();
            {
                float s = 0.f;
                #pragma unroll
                for (int ww=0; ww<8; ww++) s += sm.a.wctx[ww][tid];
                g_ctxp[c*ED + tid] = s;
            }
            if (w == 0){
                float s = 0.f;
                #pragma unroll
                for (int k=0;k<8;k++) s += sm.a.es[l + 32*k];
                #pragma unroll
                for (int off=16; off; off>>=1) s += __shfl_xor_sync(0xffffffffu, s, off);
                if (l == 0) g_sump[c] = s;
            }
        }
        gsync(gen);

        // ======== Phase B : gate GEMM (CTAs 0..255 : 32 rowblocks x 8 batchblocks) ========
        if (c < 256){
            const int rb = c >> 3;
            const int b0 = (c & 7) * 8;
            if (tid < 8){
                int b = b0 + tid;
                float ssum = g_sump[4*b] + g_sump[4*b+1] + g_sump[4*b+2] + g_sump[4*b+3];
                sm.b.rs[tid] = __fdividef(1.f, ssum);
            }
            __syncthreads();
            const int ph = t & 1;
            for (int idx = tid; idx < 8*768; idx += 256){
                int bb = idx / 768, k = idx - bb*768;
                int b = b0 + bb;
                float v;
                if (k < 256)      v = g_pre2[(size_t)t*(BB*HD) + b*HD + k];
                else if (k < 512){
                    int d = k - 256;
                    v = (g_ctxp[(4*b)*ED+d] + g_ctxp[(4*b+1)*ED+d] +
                         g_ctxp[(4*b+2)*ED+d] + g_ctxp[(4*b+3)*ED+d]) * sm.b.rs[bb];
                } else            v = g_h[ph][b*HD + (k-512)];
                sm.b.x[bb][k] = v;
            }
            __syncthreads();
            const int rr = tid >> 3, bb = tid & 7;
            const int r = rb*32 + rr;
            float a0 = bih[r] + bhh[r], a1 = 0.f, a2 = 0.f, a3 = 0.f;
            const float4* wih = (const float4*)Wih + (size_t)r*128;
            const float4* whh = (const float4*)Whh + (size_t)r*64;
            const float4* xv  = (const float4*)sm.b.x[bb];
            #pragma unroll 4
            for (int k=0;k<128;k++){
                float4 ww = wih[k], x = xv[k];
                a0 = fmaf(ww.x, x.x, a0); a1 = fmaf(ww.y, x.y, a1);
                a2 = fmaf(ww.z, x.z, a2); a3 = fmaf(ww.w, x.w, a3);
            }
            #pragma unroll 4
            for (int k=0;k<64;k++){
                float4 ww = whh[k], x = xv[128+k];
                a0 = fmaf(ww.x, x.x, a0); a1 = fmaf(ww.y, x.y, a1);
                a2 = fmaf(ww.z, x.z, a2); a3 = fmaf(ww.w, x.w, a3);
            }
            g_gates[(r>>8)*(BB*HD) + (b0+bb)*HD + (r & 255)] = (a0+a1) + (a2+a3);
        }
        gsync(gen);

        // ======== Phase C : LSTM cell + heads + next query (CTAs 0..63) ========
        if (c < 64){
            const int b = c;
            const int j = tid;
            const int ph1 = (t+1) & 1;
            float ssum = g_sump[4*b] + g_sump[4*b+1] + g_sump[4*b+2] + g_sump[4*b+3];
            float rsum = __fdividef(1.f, ssum);
            float gi = __ldcg(&g_gates[0*(BB*HD) + b*HD + j]);
            float gf = __ldcg(&g_gates[1*(BB*HD) + b*HD + j]);
            float gg = __ldcg(&g_gates[2*(BB*HD) + b*HD + j]);
            float go = __ldcg(&g_gates[3*(BB*HD) + b*HD + j]);
            float cold = g_c[b*HD + j];
            float cn = sigm(gf)*cold + sigm(gi)*tanh_acc(gg);
            float hn = sigm(go)*tanh_acc(cn);
            g_c[b*HD + j] = cn;
            g_h[ph1][b*HD + j] = hn;
            float ctxn = (g_ctxp[(4*b)*ED+j] + g_ctxp[(4*b+1)*ED+j] +
                          g_ctxp[(4*b+2)*ED+j] + g_ctxp[(4*b+3)*ED+j]) * rsum;
            sm.c.comb[j]       = hn;
            sm.c.comb[256 + j] = ctxn;
            __syncthreads();
            const float4* cv = (const float4*)sm.c.comb;
            if (tid < 80){
                float acc = melb[tid];
                const float4* wv = (const float4*)melW + tid*128;
                #pragma unroll 4
                for (int k=0;k<128;k++){ float4 ww=wv[k], x=cv[k]; acc += ww.x*x.x+ww.y*x.y+ww.z*x.z+ww.w*x.w; }
                out[(b*TO + t)*NM + tid] = acc;
            } else if (tid == 80){
                float acc = stopb[0];
                const float4* wv = (const float4*)stopW;
                for (int k=0;k<128;k++){ float4 ww=wv[k], x=cv[k]; acc += ww.x*x.x+ww.y*x.y+ww.z*x.z+ww.w*x.w; }
                out[BB*TO*NM + b*TO + t] = acc;
            }
            {
                float acc = bdec[tid];
                const float4* wv = (const float4*)Wdec + tid*64;
                #pragma unroll 4
                for (int k=0;k<64;k++){ float4 ww=wv[k], x=cv[k]; acc += ww.x*x.x+ww.y*x.y+ww.z*x.z+ww.w*x.w; }
                g_q[b*AD + tid] = acc;
            }
        }
        gsync(gen);
    }
}

// ---------------- launch ----------------
extern "C" void kernel_launch(void* const* d_in, const int* in_sizes, int n_in,
                              void* d_out, int out_size){
    (void)in_sizes; (void)n_in; (void)out_size;
    const float* enc  = (const float*)d_in[0];
    const float* tm   = (const float*)d_in[1];
    const float* Wenc = (const float*)d_in[2];
    const float* benc = (const float*)d_in[3];
    const float* Wdec = (const float*)d_in[4];
    const float* bdec = (const float*)d_in[5];
    const float* vw   = (const float*)d_in[6];
    const float* vb   = (const float*)d_in[7];
    const float* W1   = (const float*)d_in[8];
    const float* b1   = (const float*)d_in[9];
    const float* W2   = (const float*)d_in[10];
    const float* b2   = (const float*)d_in[11];
    const float* Wih  = (const float*)d_in[12];
    const float* Whh  = (const float*)d_in[13];
    const float* bih  = (const float*)d_in[14];
    const float* bhh  = (const float*)d_in[15];
    const float* melW = (const float*)d_in[16];
    const float* melb = (const float*)d_in[17];
    const float* stopW= (const float*)d_in[18];
    const float* stopb= (const float*)d_in[19];
    const float* mask = (const float*)d_in[20];
    float* out = (float*)d_out;

    k_prep_enc<<<dim3(64,64),256>>>(enc, Wenc, benc);
    k_prenet  <<<dim3(40,64),256>>>(tm, W1, b1, W2, b2);
    k_init    <<<64,256>>>(bdec);
    k_main    <<<NCTA,256>>>(mask, vw, vb, Wih, Whh, bih, bhh, Wdec, bdec,
                             melW, melb, stopW, stopb, out);
}

// round 5
// speedup vs baseline: 1.5187x; 1.1294x over previous
#include <cuda_runtime.h>
#include <cuda_fp16.h>

#define BB 64
#define TE 1024
#define TO 1000
#define AD 256
#define ED 256
#define HD 256
#define NM 80
#define NCTA 256

// ---------------- static device scratch ----------------
__device__ __half g_attn_t[BB*AD*TE];       // 32 MB : fp16 enc projection, TRANSPOSED [b][a][t]
__device__ __half g_enc_h [BB*TE*ED];       // 32 MB : fp16 enc_outputs [b][t][d]
__device__ float  g_pre2  [TO*BB*HD];       // 65.5MB: prenet(all steps) [t][b][k]
__device__ float  g_gpre  [(size_t)TO*4*HD*BB]; // 262MB: gate partial (pre+biases) [t][r][b]
__device__ float  g_q     [BB*AD];
__device__ float  g_h     [2][BB*HD];
__device__ float  g_c     [BB*HD];
__device__ float  g_ghh   [4*HD*BB];        // Whh @ h_t   [r][b]
__device__ float  g_ctxp  [128*ED];         // per (b, t-half) ctx partials
__device__ float  g_sump  [128];
__device__ float  g_gates [4*BB*HD];        // [gt][b][j]
__device__ volatile unsigned g_arrive;

__device__ __forceinline__ float tanh_acc(float x){
    x = fminf(fmaxf(x, -15.f), 15.f);
    float e = __expf(2.f*x);
    return __fdividef(e - 1.f, e + 1.f);
}
__device__ __forceinline__ float sigm(float x){
    return __fdividef(1.f, 1.f + __expf(-x));
}

// ---------------- prologue 1: enc projection (fp16, transposed) + enc fp16 copy ----
__global__ void __launch_bounds__(256) k_prep_enc(const float* __restrict__ enc,
                                                  const float* __restrict__ Wenc,
                                                  const float* __restrict__ benc){
    __shared__ float4 enc_s[16][64];
    int tid = threadIdx.x;
    int b  = blockIdx.y;
    int t0 = blockIdx.x * 16;
    int base = (b*TE + t0)*ED;
    const float4* ev = (const float4*)(enc + base);
    for (int idx = tid; idx < 16*64; idx += 256) enc_s[idx>>6][idx&63] = ev[idx];
    for (int idx = tid; idx < 16*ED; idx += 256) g_enc_h[base+idx] = __float2half(enc[base+idx]);
    __syncthreads();
    float acc[16];
    #pragma unroll
    for (int i=0;i<16;i++) acc[i]=0.f;
    const float4* wv = (const float4*)Wenc + tid*64;
    for (int e=0;e<64;e++){
        float4 w = wv[e];
        #pragma unroll
        for (int i=0;i<16;i++){
            float4 x = enc_s[i][e];
            acc[i] += w.x*x.x + w.y*x.y + w.z*x.z + w.w*x.w;
        }
    }
    float bv = benc[tid];
    #pragma unroll
    for (int i=0;i<16;i++)
        g_attn_t[((size_t)(b*AD + tid))*TE + t0 + i] = __float2half(acc[i] + bv);
}

// ---------------- prologue 2: prenet for all steps ----------------
#define TT 25
__global__ void __launch_bounds__(256) k_prenet(const float* __restrict__ tm,
                                                const float* __restrict__ W1, const float* __restrict__ b1,
                                                const float* __restrict__ W2, const float* __restrict__ b2){
    __shared__ float prev_s[TT][80];
    __shared__ float pre1_s[TT][256];
    int tid = threadIdx.x;
    int b  = blockIdx.y;
    int t0 = blockIdx.x * TT;
    for (int idx = tid; idx < TT*80; idx += 256){
        int tt = idx/80, m = idx%80;
        int t = t0 + tt;
        prev_s[tt][m] = (t==0) ? 0.f : tm[(b*TO + (t-1))*NM + m];
    }
    __syncthreads();
    float acc[TT];
    #pragma unroll
    for (int i=0;i<TT;i++) acc[i]=0.f;
    {
        const float4* w1v = (const float4*)W1 + tid*20;
        for (int m=0;m<20;m++){
            float4 w = w1v[m];
            #pragma unroll
            for (int i=0;i<TT;i++){
                float4 x = ((const float4*)prev_s[i])[m];
                acc[i] += w.x*x.x + w.y*x.y + w.z*x.z + w.w*x.w;
            }
        }
    }
    float bv1 = b1[tid];
    #pragma unroll
    for (int i=0;i<TT;i++) pre1_s[i][tid] = fmaxf(acc[i] + bv1, 0.f);
    __syncthreads();
    #pragma unroll
    for (int i=0;i<TT;i++) acc[i]=0.f;
    {
        const float4* w2v = (const float4*)W2 + tid*64;
        for (int m=0;m<64;m++){
            float4 w = w2v[m];
            #pragma unroll
            for (int i=0;i<TT;i++){
                float4 x = ((const float4*)pre1_s[i])[m];
                acc[i] += w.x*x.x + w.y*x.y + w.z*x.z + w.w*x.w;
            }
        }
    }
    float bv2 = b2[tid];
    #pragma unroll
    for (int i=0;i<TT;i++) g_pre2[(size_t)(t0+i)*(BB*HD) + b*HD + tid] = fmaxf(acc[i] + bv2, 0.f);
}

// ---------------- prologue 3: gpre[t][r][b] = Wih[:, :256] @ pre2[t] + bih + bhh ----
__global__ void __launch_bounds__(256) k_pregate(const float* __restrict__ Wih,
                                                 const float* __restrict__ bih,
                                                 const float* __restrict__ bhh){
    __shared__ float Xs[64][65];
    __shared__ float Ws[64][65];
    int tid = threadIdx.x;
    int n0 = blockIdx.x*64;              // gate row block
    int m0 = blockIdx.y*64;              // M = t*64+b block
    int tx = tid & 15, ty = tid >> 4;
    float acc[4][4];
    #pragma unroll
    for (int i=0;i<4;i++)
        #pragma unroll
        for (int j=0;j<4;j++) acc[i][j]=0.f;
    for (int k0=0;k0<256;k0+=64){
        for (int i=tid;i<64*64;i+=256){
            int mm=i>>6, kk=i&63;
            Xs[mm][kk] = g_pre2[(size_t)(m0+mm)*HD + k0+kk];
            Ws[mm][kk] = Wih[(size_t)(n0+mm)*512 + k0+kk];
        }
        __syncthreads();
        for (int k=0;k<64;k++){
            float xr[4], wr[4];
            #pragma unroll
            for (int i=0;i<4;i++){ xr[i]=Xs[ty*4+i][k]; wr[i]=Ws[tx*4+i][k]; }
            #pragma unroll
            for (int i=0;i<4;i++)
                #pragma unroll
                for (int j=0;j<4;j++) acc[i][j] = fmaf(xr[i], wr[j], acc[i][j]);
        }
        __syncthreads();
    }
    #pragma unroll
    for (int i=0;i<4;i++){
        int m = m0 + ty*4 + i; int t = m>>6, b = m&63;
        #pragma unroll
        for (int j=0;j<4;j++){
            int r = n0 + tx*4 + j;
            g_gpre[((size_t)t*1024 + r)*64 + b] = acc[i][j] + bih[r] + bhh[r];
        }
    }
}

// ---------------- prologue 4: init state + barrier counter ----------------
__global__ void k_init(const float* __restrict__ bdec){
    int b = blockIdx.x, tid = threadIdx.x;
    g_h[0][b*HD+tid] = 0.f;
    g_c[b*HD+tid]    = 0.f;
    g_q[b*AD+tid]    = bdec[tid];     // h=0 -> q = b_dec
    if (b==0 && tid==0) g_arrive = 0u;
}

// ---------------- grid barrier ----------------
__device__ __forceinline__ void gsync(unsigned &gen){
    __threadfence();
    __syncthreads();
    if (threadIdx.x == 0){
        atomicAdd((unsigned*)&g_arrive, 1u);
        gen += NCTA;
        while (g_arrive < gen) { }
    }
    __syncthreads();
}

// ---------------- persistent main kernel ----------------
struct SA { __half2 qh2[256]; float v[256]; float es[512]; float wctx[8][256]; };
struct SG { float x[8][260]; };
struct SP { float ctxn[8][260]; float rs[8]; };
struct SC { float comb[512]; };
union  SU { SA a; SG g; SP p; SC c; };

__global__ void __launch_bounds__(256,2) k_main(
        const float* __restrict__ mask, const float* __restrict__ vw, const float* __restrict__ vb,
        const float* __restrict__ Wih,  const float* __restrict__ Whh,
        const float* __restrict__ Wdec, const float* __restrict__ bdec,
        const float* __restrict__ melW, const float* __restrict__ melb,
        const float* __restrict__ stopW,const float* __restrict__ stopb,
        float* __restrict__ out){
    __shared__ SU sm;
    const int c   = blockIdx.x;
    const int tid = threadIdx.x;
    const int l   = tid & 31, w = tid >> 5;
    unsigned gen = 0;
    const float vb0 = vb[0];

    for (int t = 0; t < TO; t++){
        // ===== Phase 1a : attention (CTAs 0..127 : b = c>>1, half = c&1) =====
        if (c < 128){
            const int b = c >> 1, half = c & 1;
            sm.a.qh2[tid] = __half2half2(__float2half(__ldcg(&g_q[b*AD + tid])));
            sm.a.v[tid]   = vw[tid];
            __syncthreads();
            const int tpos = half*512 + w*64 + 2*l;     // even t for this thread
            // ---- energy over all 256 a (no cross-warp reduce) ----
            float2 acc0 = make_float2(0.f,0.f), acc1 = make_float2(0.f,0.f);
            {
                const __half2* p = ((const __half2*)g_attn_t)
                                 + ((((size_t)b)*AD*TE + tpos) >> 1);
                #pragma unroll 4
                for (int a = 0; a < 256; a += 2){
                    __half2 x0 = __ldcg(p + (size_t)a*(TE/2));
                    __half2 x1 = __ldcg(p + (size_t)(a+1)*(TE/2));
                    x0 = __hadd2(x0, sm.a.qh2[a]);
                    x1 = __hadd2(x1, sm.a.qh2[a+1]);
                    unsigned xi0 = *(unsigned*)&x0, ti0;
                    unsigned xi1 = *(unsigned*)&x1, ti1;
                    asm("tanh.approx.f16x2 %0, %1;" : "=r"(ti0) : "r"(xi0));
                    asm("tanh.approx.f16x2 %0, %1;" : "=r"(ti1) : "r"(xi1));
                    float2 t0 = __half22float2(*(__half2*)&ti0);
                    float2 t1 = __half22float2(*(__half2*)&ti1);
                    float v0 = sm.a.v[a], v1 = sm.a.v[a+1];
                    acc0.x = fmaf(v0, t0.x, acc0.x); acc0.y = fmaf(v0, t0.y, acc0.y);
                    acc1.x = fmaf(v1, t1.x, acc1.x); acc1.y = fmaf(v1, t1.y, acc1.y);
                }
            }
            {
                float mk0 = mask[b*TE + tpos];
                float mk1 = mask[b*TE + tpos + 1];
                float e0 = (mk0 != 0.f) ? __expf(acc0.x + acc1.x + vb0) : 0.f;
                float e1 = (mk1 != 0.f) ? __expf(acc0.y + acc1.y + vb0) : 0.f;
                sm.a.es[w*64 + 2*l]     = e0;
                sm.a.es[w*64 + 2*l + 1] = e1;
            }
            __syncwarp();
            // ---- context partials: warp w covers its own 64 t (branchless) ----
            float2 ca[4];
            #pragma unroll
            for (int k=0;k<4;k++) ca[k] = make_float2(0.f,0.f);
            {
                const __half2* pe = ((const __half2*)g_enc_h)
                                  + ((((size_t)(b*TE + half*512 + w*64))*ED) >> 1) + l;
                #pragma unroll 2
                for (int i=0;i<64;i++){
                    float e = sm.a.es[w*64 + i];
                    #pragma unroll
                    for (int k=0;k<4;k++){
                        float2 f = __half22float2(__ldcg(pe + k*32));
                        ca[k].x = fmaf(e, f.x, ca[k].x);
                        ca[k].y = fmaf(e, f.y, ca[k].y);
                    }
                    pe += ED/2;
                }
            }
            #pragma unroll
            for (int k=0;k<4;k++){
                sm.a.wctx[w][2*(l+32*k)]   = ca[k].x;
                sm.a.wctx[w][2*(l+32*k)+1] = ca[k].y;
            }
            __syncthreads();
            {
                float s = 0.f;
                #pragma unroll
                for (int ww=0; ww<8; ww++) s += sm.a.wctx[ww][tid];
                g_ctxp[c*ED + tid] = s;
            }
            if (w == 0){
                float s = 0.f;
                #pragma unroll
                for (int k=0;k<16;k++) s += sm.a.es[l + 32*k];
                #pragma unroll
                for (int off=16; off; off>>=1) s += __shfl_xor_sync(0xffffffffu, s, off);
                if (l == 0) g_sump[c] = s;
            }
        }
        // ===== Phase 1b : ghh = Whh @ h_t (CTAs 128..255) =====
        else {
            const int i  = c - 128;
            const int r0 = (i >> 3) * 64;       // 16 rowgroups x 64 rows
            const int b0 = (i & 7) * 8;         // 8 bgroups x 8 b
            const int ph = t & 1;
            for (int idx = tid; idx < 8*256; idx += 256){
                int bb = idx >> 8, k = idx & 255;
                sm.g.x[bb][k] = __ldcg(&g_h[ph][(b0+bb)*HD + k]);
            }
            __syncthreads();
            const int bb = tid & 7, rr = tid >> 3;   // rr: 0..31
            const int r1 = r0 + rr, r2 = r0 + 32 + rr;
            float a0 = 0.f, a1 = 0.f;
            const float4* w0 = (const float4*)Whh + (size_t)r1*64;
            const float4* w1 = (const float4*)Whh + (size_t)r2*64;
            const float4* xv = (const float4*)sm.g.x[bb];
            #pragma unroll 4
            for (int k=0;k<64;k++){
                float4 ww0 = w0[k], ww1 = w1[k], x = xv[k];
                a0 = fmaf(ww0.x,x.x,a0); a0 = fmaf(ww0.y,x.y,a0);
                a0 = fmaf(ww0.z,x.z,a0); a0 = fmaf(ww0.w,x.w,a0);
                a1 = fmaf(ww1.x,x.x,a1); a1 = fmaf(ww1.y,x.y,a1);
                a1 = fmaf(ww1.z,x.z,a1); a1 = fmaf(ww1.w,x.w,a1);
            }
            g_ghh[r1*64 + b0+bb] = a0;
            g_ghh[r2*64 + b0+bb] = a1;
        }
        gsync(gen);

        // ===== Phase 2 : gates = gpre[t] + ghh + Wih[:,256:512] @ ctx =====
        {
            const int r0 = (c >> 3) * 32;       // 32 rowblocks x 32 rows
            const int b0 = (c & 7) * 8;         // 8 bblocks x 8 b
            if (tid < 8){
                int b = b0 + tid;
                float ssum = __ldcg(&g_sump[2*b]) + __ldcg(&g_sump[2*b+1]);
                sm.p.rs[tid] = __fdividef(1.f, ssum);
            }
            __syncthreads();
            for (int idx = tid; idx < 8*256; idx += 256){
                int bb = idx >> 8, d = idx & 255;
                int b = b0 + bb;
                sm.p.ctxn[bb][d] = (__ldcg(&g_ctxp[(2*b)*ED + d]) +
                                    __ldcg(&g_ctxp[(2*b+1)*ED + d])) * sm.p.rs[bb];
            }
            __syncthreads();
            const int bb = tid & 7, rr = tid >> 3;
            const int r = r0 + rr, b = b0 + bb;
            float acc = g_gpre[((size_t)t*1024 + r)*64 + b] + __ldcg(&g_ghh[r*64 + b]);
            const float4* wv = (const float4*)Wih + (size_t)r*128 + 64;   // cols 256..511
            const float4* xv = (const float4*)sm.p.ctxn[bb];
            #pragma unroll 4
            for (int k=0;k<64;k++){
                float4 ww = wv[k], x = xv[k];
                acc = fmaf(ww.x,x.x,acc); acc = fmaf(ww.y,x.y,acc);
                acc = fmaf(ww.z,x.z,acc); acc = fmaf(ww.w,x.w,acc);
            }
            g_gates[(r>>8)*(BB*HD) + b*HD + (r & 255)] = acc;
        }
        gsync(gen);

        // ===== Phase 3 : LSTM cell + heads + next query (CTAs 0..63) =====
        if (c < 64){
            const int b = c;
            const int j = tid;
            const int ph1 = (t+1) & 1;
            float ssum = __ldcg(&g_sump[2*b]) + __ldcg(&g_sump[2*b+1]);
            float rsum = __fdividef(1.f, ssum);
            float gi = __ldcg(&g_gates[0*(BB*HD) + b*HD + j]);
            float gf = __ldcg(&g_gates[1*(BB*HD) + b*HD + j]);
            float gg = __ldcg(&g_gates[2*(BB*HD) + b*HD + j]);
            float go = __ldcg(&g_gates[3*(BB*HD) + b*HD + j]);
            float cold = g_c[b*HD + j];
            float cn = sigm(gf)*cold + sigm(gi)*tanh_acc(gg);
            float hn = sigm(go)*tanh_acc(cn);
            g_c[b*HD + j] = cn;
            g_h[ph1][b*HD + j] = hn;
            float ctxn = (__ldcg(&g_ctxp[(2*b)*ED + j]) +
                          __ldcg(&g_ctxp[(2*b+1)*ED + j])) * rsum;
            sm.c.comb[j]       = hn;
            sm.c.comb[256 + j] = ctxn;
            __syncthreads();
            const float4* cv = (const float4*)sm.c.comb;
            if (tid < 80){
                float acc = melb[tid];
                const float4* wv = (const float4*)melW + tid*128;
                #pragma unroll 4
                for (int k=0;k<128;k++){ float4 ww=wv[k], x=cv[k]; acc += ww.x*x.x+ww.y*x.y+ww.z*x.z+ww.w*x.w; }
                out[(b*TO + t)*NM + tid] = acc;
            } else if (tid == 80){
                float acc = stopb[0];
                const float4* wv = (const float4*)stopW;
                for (int k=0;k<128;k++){ float4 ww=wv[k], x=cv[k]; acc += ww.x*x.x+ww.y*x.y+ww.z*x.z+ww.w*x.w; }
                out[BB*TO*NM + b*TO + t] = acc;
            }
            {
                float acc = bdec[tid];
                const float4* wv = (const float4*)Wdec + tid*64;
                #pragma unroll 4
                for (int k=0;k<64;k++){ float4 ww=wv[k], x=cv[k]; acc += ww.x*x.x+ww.y*x.y+ww.z*x.z+ww.w*x.w; }
                g_q[b*AD + tid] = acc;
            }
        }
        gsync(gen);
    }
}

// ---------------- launch ----------------
extern "C" void kernel_launch(void* const* d_in, const int* in_sizes, int n_in,
                              void* d_out, int out_size){
    (void)in_sizes; (void)n_in; (void)out_size;
    const float* enc  = (const float*)d_in[0];
    const float* tm   = (const float*)d_in[1];
    const float* Wenc = (const float*)d_in[2];
    const float* benc = (const float*)d_in[3];
    const float* Wdec = (const float*)d_in[4];
    const float* bdec = (const float*)d_in[5];
    const float* vw   = (const float*)d_in[6];
    const float* vb   = (const float*)d_in[7];
    const float* W1   = (const float*)d_in[8];
    const float* b1   = (const float*)d_in[9];
    const float* W2   = (const float*)d_in[10];
    const float* b2   = (const float*)d_in[11];
    const float* Wih  = (const float*)d_in[12];
    const float* Whh  = (const float*)d_in[13];
    const float* bih  = (const float*)d_in[14];
    const float* bhh  = (const float*)d_in[15];
    const float* melW = (const float*)d_in[16];
    const float* melb = (const float*)d_in[17];
    const float* stopW= (const float*)d_in[18];
    const float* stopb= (const float*)d_in[19];
    const float* mask = (const float*)d_in[20];
    float* out = (float*)d_out;

    k_prep_enc<<<dim3(64,64),256>>>(enc, Wenc, benc);
    k_prenet  <<<dim3(40,64),256>>>(tm, W1, b1, W2, b2);
    k_pregate <<<dim3(16,1000),256>>>(Wih, bih, bhh);
    k_init    <<<64,256>>>(bdec);
    k_main    <<<NCTA,256>>>(mask, vw, vb, Wih, Whh, Wdec, bdec,
                             melW, melb, stopW, stopb, out);
}

// round 7
// speedup vs baseline: 1.5239x; 1.0034x over previous
#include <cuda_runtime.h>
#include <cuda_fp16.h>

#define BB 64
#define TE 1024
#define TO 1000
#define AD 256
#define ED 256
#define HD 256
#define NM 80
#define NCTA 256

// ---------------- static device scratch ----------------
__device__ __half g_attn_t[(size_t)BB*AD*TE];   // 32 MB : fp16 enc projection, TRANSPOSED [b][a][t]
__device__ __half g_enc_h [(size_t)BB*TE*ED];   // 32 MB : fp16 enc_outputs [b][t][d]
__device__ float  g_pre2  [(size_t)TO*BB*HD];   // prenet(all steps) [t*64+b][k]
__device__ float  g_gpre  [(size_t)TO*4*HD*BB]; // gate partial (pre+biases) [t][r][b]
__device__ float  g_q     [BB*AD];
__device__ float  g_h     [2][BB*HD];
__device__ float  g_ctxp  [256*ED];             // per (b, quarter) ctx partials (permuted layout)
__device__ float  g_sump  [256];
__device__ float  g_gates [4*BB*HD];            // [gt][b][j]
__device__ int    g_len   [BB];
__device__ volatile unsigned g_arrive;

__device__ __forceinline__ float tanh_acc(float x){
    x = fminf(fmaxf(x, -15.f), 15.f);
    float e = __expf(2.f*x);
    return __fdividef(e - 1.f, e + 1.f);
}
__device__ __forceinline__ float sigm(float x){
    return __fdividef(1.f, 1.f + __expf(-x));
}

// ---------------- prologue 1: enc projection (fp16, transposed) + enc fp16 copy ----
__global__ void __launch_bounds__(256) k_prep_enc(const float* __restrict__ enc,
                                                  const float* __restrict__ Wenc,
                                                  const float* __restrict__ benc){
    __shared__ float4 enc_s[16][64];
    int tid = threadIdx.x;
    int b  = blockIdx.y;
    int t0 = blockIdx.x * 16;
    int base = (b*TE + t0)*ED;
    const float4* ev = (const float4*)(enc + base);
    for (int idx = tid; idx < 16*64; idx += 256) enc_s[idx>>6][idx&63] = ev[idx];
    for (int idx = tid; idx < 16*ED; idx += 256) g_enc_h[base+idx] = __float2half(enc[base+idx]);
    __syncthreads();
    float acc[16];
    #pragma unroll
    for (int i=0;i<16;i++) acc[i]=0.f;
    const float4* wv = (const float4*)Wenc + tid*64;
    for (int e=0;e<64;e++){
        float4 w = wv[e];
        #pragma unroll
        for (int i=0;i<16;i++){
            float4 x = enc_s[i][e];
            acc[i] += w.x*x.x + w.y*x.y + w.z*x.z + w.w*x.w;
        }
    }
    float bv = benc[tid];
    #pragma unroll
    for (int i=0;i<16;i++)
        g_attn_t[((size_t)(b*AD + tid))*TE + t0 + i] = __float2half(acc[i] + bv);
}

// ---------------- prologue 2: prenet for all steps ----------------
#define TT 25
__global__ void __launch_bounds__(256) k_prenet(const float* __restrict__ tm,
                                                const float* __restrict__ W1, const float* __restrict__ b1,
                                                const float* __restrict__ W2, const float* __restrict__ b2){
    __shared__ float prev_s[TT][80];
    __shared__ float pre1_s[TT][256];
    int tid = threadIdx.x;
    int b  = blockIdx.y;
    int t0 = blockIdx.x * TT;
    for (int idx = tid; idx < TT*80; idx += 256){
        int tt = idx/80, m = idx%80;
        int t = t0 + tt;
        prev_s[tt][m] = (t==0) ? 0.f : tm[(b*TO + (t-1))*NM + m];
    }
    __syncthreads();
    float acc[TT];
    #pragma unroll
    for (int i=0;i<TT;i++) acc[i]=0.f;
    {
        const float4* w1v = (const float4*)W1 + tid*20;
        for (int m=0;m<20;m++){
            float4 w = w1v[m];
            #pragma unroll
            for (int i=0;i<TT;i++){
                float4 x = ((const float4*)prev_s[i])[m];
                acc[i] += w.x*x.x + w.y*x.y + w.z*x.z + w.w*x.w;
            }
        }
    }
    float bv1 = b1[tid];
    #pragma unroll
    for (int i=0;i<TT;i++) pre1_s[i][tid] = fmaxf(acc[i] + bv1, 0.f);
    __syncthreads();
    #pragma unroll
    for (int i=0;i<TT;i++) acc[i]=0.f;
    {
        const float4* w2v = (const float4*)W2 + tid*64;
        for (int m=0;m<64;m++){
            float4 w = w2v[m];
            #pragma unroll
            for (int i=0;i<TT;i++){
                float4 x = ((const float4*)pre1_s[i])[m];
                acc[i] += w.x*x.x + w.y*x.y + w.z*x.z + w.w*x.w;
            }
        }
    }
    float bv2 = b2[tid];
    #pragma unroll
    for (int i=0;i<TT;i++) g_pre2[(size_t)(t0+i)*(BB*HD) + b*HD + tid] = fmaxf(acc[i] + bv2, 0.f);
}

// ---------------- prologue 3: gpre[t][r][b] = Wih[:, :256] @ pre2[t] + bih + bhh ----
__global__ void __launch_bounds__(256) k_pregate(const float* __restrict__ Wih,
                                                 const float* __restrict__ bih,
                                                 const float* __restrict__ bhh){
    __shared__ float Xs[64][65];
    __shared__ float Ws[64][65];
    int tid = threadIdx.x;
    int n0 = blockIdx.x*64;              // gate row block
    int m0 = blockIdx.y*64;              // M = t*64+b block (one t per block)
    int tx = tid & 15, ty = tid >> 4;
    float acc[4][4];
    #pragma unroll
    for (int i=0;i<4;i++)
        #pragma unroll
        for (int j=0;j<4;j++) acc[i][j]=0.f;
    for (int k0=0;k0<256;k0+=64){
        for (int i=tid;i<64*64;i+=256){
            int mm=i>>6, kk=i&63;
            Xs[mm][kk] = g_pre2[(size_t)(m0+mm)*HD + k0+kk];
            Ws[mm][kk] = Wih[(size_t)(n0+mm)*512 + k0+kk];
        }
        __syncthreads();
        for (int k=0;k<64;k++){
            float xr[4], wr[4];
            #pragma unroll
            for (int i=0;i<4;i++){ xr[i]=Xs[ty*4+i][k]; wr[i]=Ws[tx*4+i][k]; }
            #pragma unroll
            for (int i=0;i<4;i++)
                #pragma unroll
                for (int j=0;j<4;j++) acc[i][j] = fmaf(xr[i], wr[j], acc[i][j]);
        }
        __syncthreads();
    }
    #pragma unroll
    for (int i=0;i<4;i++){
        int m = m0 + ty*4 + i; int t = m>>6, b = m&63;
        #pragma unroll
        for (int j=0;j<4;j++){
            int r = n0 + tx*4 + j;
            g_gpre[((size_t)t*1024 + r)*64 + b] = acc[i][j] + bih[r] + bhh[r];
        }
    }
}

// ---------------- prologue 4: init state, lengths, barrier ----------------
__global__ void k_init(const float* __restrict__ bdec, const float* __restrict__ mask){
    __shared__ float red[256];
    int b = blockIdx.x, tid = threadIdx.x;
    g_h[0][b*HD+tid] = 0.f;
    g_q[b*AD+tid]    = bdec[tid];     // h=0 -> q = b_dec
    float s = 0.f;
    for (int i=tid;i<TE;i+=256) s += mask[b*TE+i];
    red[tid]=s; __syncthreads();
    for (int off=128; off; off>>=1){ if (tid<off) red[tid]+=red[tid+off]; __syncthreads(); }
    if (tid==0) g_len[b] = (int)(red[0] + 0.5f);
    if (b==0 && tid==0) g_arrive = 0u;
}

// ---------------- grid barrier ----------------
__device__ __forceinline__ void gsync(unsigned &gen){
    __threadfence();
    __syncthreads();
    if (threadIdx.x == 0){
        atomicAdd((unsigned*)&g_arrive, 1u);
        gen += NCTA;
        while (g_arrive < gen) { }
    }
    __syncthreads();
}

// ---------------- persistent main kernel ----------------
struct SA { __half2 qh[AD]; float v[AD]; float ep[8][8][32]; float es[256]; float red[8]; float wctx[8][8][32]; };
struct SB { float x[8][516]; float rs[8]; };
struct SC { float comb[512]; };
union  SU { SA a; SB b; SC c; };

__global__ void __launch_bounds__(256,2) k_main(
        const float* __restrict__ vw,  const float* __restrict__ vb,
        const float* __restrict__ Wih, const float* __restrict__ Whh,
        const float* __restrict__ Wdec, const float* __restrict__ bdec,
        const float* __restrict__ melW, const float* __restrict__ melb,
        const float* __restrict__ stopW, const float* __restrict__ stopb,
        float* __restrict__ out){
    __shared__ SU sm;
    const int c   = blockIdx.x;
    const int tid = threadIdx.x;
    const int l   = tid & 31, w = tid >> 5;
    unsigned gen = 0;
    const float vb0 = vb[0];
    float c_state = 0.f;                 // LSTM cell state lives in registers (CTAs 0..63)

    for (int t = 0; t < TO; t++){
        // ======== Phase A : attention — ALL 256 CTAs (b = c>>2, quarter = c&3) ========
        {
            const int b  = c >> 2, qt = c & 3;
            const int len = g_len[b];
            sm.a.qh[tid] = __half2half2(__float2half(__ldcg(&g_q[b*AD + tid])));
            sm.a.v[tid]  = vw[tid];
            __syncthreads();
            // ---- energy: warp w owns a = w + 8k; lane l owns t-chunk [qt*256 + l*8, +8) ----
            float e8[8];
            #pragma unroll
            for (int i=0;i<8;i++) e8[i] = 0.f;
            if (qt*256 < len){
                const uint4* ap = (const uint4*)g_attn_t;
                const size_t base = (((size_t)b*AD)*TE + qt*256) >> 3;   // uint4 units
                #pragma unroll 4
                for (int k = 0; k < 32; k++){
                    const int a = w + 8*k;
                    uint4 x = __ldcg(ap + base + (size_t)a*(TE>>3) + l);
                    __half2 qa = sm.a.qh[a];
                    float  va = sm.a.v[a];
                    __half2 h0 = __hadd2(*(__half2*)&x.x, qa);
                    __half2 h1 = __hadd2(*(__half2*)&x.y, qa);
                    __half2 h2 = __hadd2(*(__half2*)&x.z, qa);
                    __half2 h3 = __hadd2(*(__half2*)&x.w, qa);
                    unsigned r0,r1,r2,r3;
                    asm("tanh.approx.f16x2 %0, %1;" : "=r"(r0) : "r"(*(unsigned*)&h0));
                    asm("tanh.approx.f16x2 %0, %1;" : "=r"(r1) : "r"(*(unsigned*)&h1));
                    asm("tanh.approx.f16x2 %0, %1;" : "=r"(r2) : "r"(*(unsigned*)&h2));
                    asm("tanh.approx.f16x2 %0, %1;" : "=r"(r3) : "r"(*(unsigned*)&h3));
                    float2 f0 = __half22float2(*(__half2*)&r0);
                    float2 f1 = __half22float2(*(__half2*)&r1);
                    float2 f2 = __half22float2(*(__half2*)&r2);
                    float2 f3 = __half22float2(*(__half2*)&r3);
                    e8[0] = fmaf(va, f0.x, e8[0]); e8[1] = fmaf(va, f0.y, e8[1]);
                    e8[2] = fmaf(va, f1.x, e8[2]); e8[3] = fmaf(va, f1.y, e8[3]);
                    e8[4] = fmaf(va, f2.x, e8[4]); e8[5] = fmaf(va, f2.y, e8[5]);
                    e8[6] = fmaf(va, f3.x, e8[6]); e8[7] = fmaf(va, f3.y, e8[7]);
                }
            }
            #pragma unroll
            for (int i=0;i<8;i++) sm.a.ep[w][i][l] = e8[i];
            __syncthreads();
            // ---- combine across warps, exp, mask ----
            float e;
            {
                const int l2 = tid & 31, i2 = tid >> 5;
                const int tg = qt*256 + l2*8 + i2;
                float s = 0.f;
                #pragma unroll
                for (int ww=0; ww<8; ww++) s += sm.a.ep[ww][i2][l2];
                e = (tg < len) ? __expf(s + vb0) : 0.f;
                sm.a.es[i2*32 + l2] = e;          // es[(t&7)*32 + (t>>3)]
            }
            {
                float s = e;
                #pragma unroll
                for (int off=16; off; off>>=1) s += __shfl_xor_sync(0xffffffffu, s, off);
                if (l == 0) sm.a.red[w] = s;
            }
            __syncthreads();
            if (tid == 0){
                float ss = 0.f;
                #pragma unroll
                for (int ww=0; ww<8; ww++) ss += sm.a.red[ww];
                g_sump[c] = ss;
            }
            // ---- context: warp w owns t-range [qt*256 + w*32, +32), lane l owns d-chunk l*8 ----
            float ca[8];
            #pragma unroll
            for (int i=0;i<8;i++) ca[i] = 0.f;
            {
                const int baset = qt*256 + w*32;
                int iters = len - baset;
                iters = iters < 0 ? 0 : (iters > 32 ? 32 : iters);
                const uint4* ep4 = (const uint4*)g_enc_h + (((size_t)(b*TE + baset)) << 5) + l;
                #pragma unroll 4
                for (int i=0;i<iters;i++){
                    float ev = sm.a.es[(i&7)*32 + w*4 + (i>>3)];
                    uint4 x = __ldcg(ep4 + i*32);
                    float2 f0 = __half22float2(*(__half2*)&x.x);
                    float2 f1 = __half22float2(*(__half2*)&x.y);
                    float2 f2 = __half22float2(*(__half2*)&x.z);
                    float2 f3 = __half22float2(*(__half2*)&x.w);
                    ca[0] = fmaf(ev, f0.x, ca[0]); ca[1] = fmaf(ev, f0.y, ca[1]);
                    ca[2] = fmaf(ev, f1.x, ca[2]); ca[3] = fmaf(ev, f1.y, ca[3]);
                    ca[4] = fmaf(ev, f2.x, ca[4]); ca[5] = fmaf(ev, f2.y, ca[5]);
                    ca[6] = fmaf(ev, f3.x, ca[6]); ca[7] = fmaf(ev, f3.y, ca[7]);
                }
            }
            #pragma unroll
            for (int i=0;i<8;i++) sm.a.wctx[w][i][l] = ca[i];
            __syncthreads();
            {
                const int l3 = tid & 31, j3 = tid >> 5;
                float s = 0.f;
                #pragma unroll
                for (int ww=0; ww<8; ww++) s += sm.a.wctx[ww][j3][l3];
                g_ctxp[c*ED + tid] = s;          // permuted: s-index = (d&7)*32 + (d>>3)
            }
        }
        gsync(gen);

        // ======== Phase 2 : gates = gpre[t] + [Wih_ctx | Whh] @ [ctx ; h] ========
        {
            const int r0 = (c >> 3) * 32;        // 32 rowblocks x 32 rows
            const int b0 = (c & 7) * 8;          // 8 bblocks x 8 b
            if (tid < 8){
                int b = b0 + tid;
                float ssum = __ldcg(&g_sump[4*b])   + __ldcg(&g_sump[4*b+1])
                           + __ldcg(&g_sump[4*b+2]) + __ldcg(&g_sump[4*b+3]);
                sm.b.rs[tid] = __fdividef(1.f, ssum);
            }
            __syncthreads();
            const int ph = t & 1;
            for (int idx = tid; idx < 8*512; idx += 256){
                int bb = idx >> 9, k = idx & 511;
                int b = b0 + bb;
                float v;
                if (k < 256){
                    int s = ((k & 7) << 5) | (k >> 3);
                    v = (__ldcg(&g_ctxp[(4*b)*ED + s])   + __ldcg(&g_ctxp[(4*b+1)*ED + s])
                       + __ldcg(&g_ctxp[(4*b+2)*ED + s]) + __ldcg(&g_ctxp[(4*b+3)*ED + s]))
                      * sm.b.rs[bb];
                } else {
                    v = __ldcg(&g_h[ph][b*HD + (k - 256)]);
                }
                sm.b.x[bb][k] = v;
            }
            __syncthreads();
            const int rr = tid >> 3, bb = tid & 7;
            const int r = r0 + rr, b = b0 + bb;
            float a0 = __ldcg(&g_gpre[((size_t)t*1024 + r)*64 + b]);
            float a1 = 0.f, a2 = 0.f, a3 = 0.f;
            const float4* w1 = (const float4*)Wih + (size_t)r*128 + 64;   // cols 256..511
            const float4* w2 = (const float4*)Whh + (size_t)r*64;
            const float4* x1 = (const float4*)sm.b.x[bb];                 // ctx
            const float4* x2 = x1 + 64;                                   // h
            #pragma unroll 4
            for (int k=0;k<64;k++){
                float4 ww = w1[k], xx = x1[k];
                a0 = fmaf(ww.x,xx.x,a0); a1 = fmaf(ww.y,xx.y,a1);
                a2 = fmaf(ww.z,xx.z,a2); a3 = fmaf(ww.w,xx.w,a3);
            }
            #pragma unroll 4
            for (int k=0;k<64;k++){
                float4 ww = w2[k], xx = x2[k];
                a0 = fmaf(ww.x,xx.x,a0); a1 = fmaf(ww.y,xx.y,a1);
                a2 = fmaf(ww.z,xx.z,a2); a3 = fmaf(ww.w,xx.w,a3);
            }
            g_gates[(r>>8)*(BB*HD) + b*HD + (r & 255)] = (a0+a1) + (a2+a3);
        }
        gsync(gen);

        // ======== Phase 3 : LSTM cell + heads + next query (CTAs 0..63) ========
        if (c < 64){
            const int b = c, j = tid;
            const int ph1 = (t+1) & 1;
            float ssum = __ldcg(&g_sump[4*b])   + __ldcg(&g_sump[4*b+1])
                       + __ldcg(&g_sump[4*b+2]) + __ldcg(&g_sump[4*b+3]);
            float rsum = __fdividef(1.f, ssum);
            float gi = __ldcg(&g_gates[0*(BB*HD) + b*HD + j]);
            float gf = __ldcg(&g_gates[1*(BB*HD) + b*HD + j]);
            float gg = __ldcg(&g_gates[2*(BB*HD) + b*HD + j]);
            float go = __ldcg(&g_gates[3*(BB*HD) + b*HD + j]);
            float cn = sigm(gf)*c_state + sigm(gi)*tanh_acc(gg);
            float hn = sigm(go)*tanh_acc(cn);
            c_state = cn;
            g_h[ph1][b*HD + j] = hn;
            int sidx = ((j & 7) << 5) | (j >> 3);
            float ctxn = (__ldcg(&g_ctxp[(4*b)*ED + sidx])   + __ldcg(&g_ctxp[(4*b+1)*ED + sidx])
                        + __ldcg(&g_ctxp[(4*b+2)*ED + sidx]) + __ldcg(&g_ctxp[(4*b+3)*ED + sidx]))
                       * rsum;
            sm.c.comb[j]       = hn;
            sm.c.comb[256 + j] = ctxn;
            __syncthreads();
            const float4* cv = (const float4*)sm.c.comb;
            if (tid < 80){
                float m0 = melb[tid], m1 = 0.f, m2 = 0.f, m3 = 0.f;
                const float4* wv = (const float4*)melW + tid*128;
                #pragma unroll 4
                for (int k=0;k<128;k++){
                    float4 ww = wv[k], xx = cv[k];
                    m0 = fmaf(ww.x,xx.x,m0); m1 = fmaf(ww.y,xx.y,m1);
                    m2 = fmaf(ww.z,xx.z,m2); m3 = fmaf(ww.w,xx.w,m3);
                }
                out[(b*TO + t)*NM + tid] = (m0+m1) + (m2+m3);
            } else if (tid == 80){
                float m0 = stopb[0], m1 = 0.f, m2 = 0.f, m3 = 0.f;
                const float4* wv = (const float4*)stopW;
                #pragma unroll 4
                for (int k=0;k<128;k++){
                    float4 ww = wv[k], xx = cv[k];
                    m0 = fmaf(ww.x,xx.x,m0); m1 = fmaf(ww.y,xx.y,m1);
                    m2 = fmaf(ww.z,xx.z,m2); m3 = fmaf(ww.w,xx.w,m3);
                }
                out[BB*TO*NM + b*TO + t] = (m0+m1) + (m2+m3);
            }
            {
                float q0 = bdec[tid], q1 = 0.f, q2 = 0.f, q3 = 0.f;
                const float4* wv = (const float4*)Wdec + tid*64;
                #pragma unroll 4
                for (int k=0;k<64;k++){
                    float4 ww = wv[k], xx = cv[k];
                    q0 = fmaf(ww.x,xx.x,q0); q1 = fmaf(ww.y,xx.y,q1);
                    q2 = fmaf(ww.z,xx.z,q2); q3 = fmaf(ww.w,xx.w,q3);
                }
                g_q[b*AD + tid] = (q0+q1) + (q2+q3);
            }
        }
        gsync(gen);
    }
}

// ---------------- launch ----------------
extern "C" void kernel_launch(void* const* d_in, const int* in_sizes, int n_in,
                              void* d_out, int out_size){
    (void)in_sizes; (void)n_in; (void)out_size;
    const float* enc  = (const float*)d_in[0];
    const float* tm   = (const float*)d_in[1];
    const float* Wenc = (const float*)d_in[2];
    const float* benc = (const float*)d_in[3];
    const float* Wdec = (const float*)d_in[4];
    const float* bdec = (const float*)d_in[5];
    const float* vw   = (const float*)d_in[6];
    const float* vb   = (const float*)d_in[7];
    const float* W1   = (const float*)d_in[8];
    const float* b1   = (const float*)d_in[9];
    const float* W2   = (const float*)d_in[10];
    const float* b2   = (const float*)d_in[11];
    const float* Wih  = (const float*)d_in[12];
    const float* Whh  = (const float*)d_in[13];
    const float* bih  = (const float*)d_in[14];
    const float* bhh  = (const float*)d_in[15];
    const float* melW = (const float*)d_in[16];
    const float* melb = (const float*)d_in[17];
    const float* stopW= (const float*)d_in[18];
    const float* stopb= (const float*)d_in[19];
    const float* mask = (const float*)d_in[20];
    float* out = (float*)d_out;

    k_prep_enc<<<dim3(64,64),256>>>(enc, Wenc, benc);
    k_prenet  <<<dim3(40,64),256>>>(tm, W1, b1, W2, b2);
    k_pregate <<<dim3(16,1000),256>>>(Wih, bih, bhh);
    k_init    <<<64,256>>>(bdec, mask);
    k_main    <<<NCTA,256>>>(vw, vb, Wih, Whh, Wdec, bdec,
                             melW, melb, stopW, stopb, out);
}

// round 9
// speedup vs baseline: 2.2244x; 1.4596x over previous
#include <cuda_runtime.h>
#include <cuda_fp16.h>

#define BB 64
#define TE 1024
#define TO 1000
#define AD 256
#define ED 256
#define HD 256
#define NM 80
#define NCTA 296

// ---------------- static device scratch ----------------
__device__ __half g_attn_t[(size_t)BB*AD*TE];   // 32 MB : fp16 enc projection, TRANSPOSED [b][a][t]
__device__ __half g_enc_h [(size_t)BB*TE*ED];   // 32 MB : fp16 enc_outputs [b][t][d]
__device__ float  g_pre2  [(size_t)TO*BB*HD];   // prenet(all steps) [t*64+b][k]
__device__ float  g_gpre  [(size_t)TO*4*HD*BB]; // gate partial (pre+biases) [t][r][b]
__device__ float  g_q     [BB*AD];
__device__ float  g_h     [2][BB*HD];
__device__ float  g_ctxp  [512*ED];             // per (b, eighth) ctx partials
__device__ float  g_sump  [512];
__device__ float  g_hhist [(size_t)TO*BB*HD];   // h history (for deferred heads)
__device__ float  g_chist [(size_t)TO*BB*ED];   // ctx history
__device__ int    g_len   [BB];
__device__ unsigned g_arrive;
__device__ unsigned g_ticketA;

__device__ __forceinline__ float tanh_acc(float x){
    x = fminf(fmaxf(x, -15.f), 15.f);
    float e = __expf(2.f*x);
    return __fdividef(e - 1.f, e + 1.f);
}
__device__ __forceinline__ float sigm(float x){
    return __fdividef(1.f, 1.f + __expf(-x));
}

// ---------------- prologue 1: enc projection (fp16, transposed) + enc fp16 copy ----
__global__ void __launch_bounds__(256) k_prep_enc(const float* __restrict__ enc,
                                                  const float* __restrict__ Wenc,
                                                  const float* __restrict__ benc){
    __shared__ float4 enc_s[16][64];
    int tid = threadIdx.x;
    int b  = blockIdx.y;
    int t0 = blockIdx.x * 16;
    int base = (b*TE + t0)*ED;
    const float4* ev = (const float4*)(enc + base);
    for (int idx = tid; idx < 16*64; idx += 256) enc_s[idx>>6][idx&63] = ev[idx];
    for (int idx = tid; idx < 16*ED; idx += 256) g_enc_h[base+idx] = __float2half(enc[base+idx]);
    __syncthreads();
    float acc[16];
    #pragma unroll
    for (int i=0;i<16;i++) acc[i]=0.f;
    const float4* wv = (const float4*)Wenc + tid*64;
    for (int e=0;e<64;e++){
        float4 w = wv[e];
        #pragma unroll
        for (int i=0;i<16;i++){
            float4 x = enc_s[i][e];
            acc[i] += w.x*x.x + w.y*x.y + w.z*x.z + w.w*x.w;
        }
    }
    float bv = benc[tid];
    #pragma unroll
    for (int i=0;i<16;i++)
        g_attn_t[((size_t)(b*AD + tid))*TE + t0 + i] = __float2half(acc[i] + bv);
}

// ---------------- prologue 2: prenet for all steps ----------------
#define TT 25
__global__ void __launch_bounds__(256) k_prenet(const float* __restrict__ tm,
                                                const float* __restrict__ W1, const float* __restrict__ b1,
                                                const float* __restrict__ W2, const float* __restrict__ b2){
    __shared__ float prev_s[TT][80];
    __shared__ float pre1_s[TT][256];
    int tid = threadIdx.x;
    int b  = blockIdx.y;
    int t0 = blockIdx.x * TT;
    for (int idx = tid; idx < TT*80; idx += 256){
        int tt = idx/80, m = idx%80;
        int t = t0 + tt;
        prev_s[tt][m] = (t==0) ? 0.f : tm[(b*TO + (t-1))*NM + m];
    }
    __syncthreads();
    float acc[TT];
    #pragma unroll
    for (int i=0;i<TT;i++) acc[i]=0.f;
    {
        const float4* w1v = (const float4*)W1 + tid*20;
        for (int m=0;m<20;m++){
            float4 w = w1v[m];
            #pragma unroll
            for (int i=0;i<TT;i++){
                float4 x = ((const float4*)prev_s[i])[m];
                acc[i] += w.x*x.x + w.y*x.y + w.z*x.z + w.w*x.w;
            }
        }
    }
    float bv1 = b1[tid];
    #pragma unroll
    for (int i=0;i<TT;i++) pre1_s[i][tid] = fmaxf(acc[i] + bv1, 0.f);
    __syncthreads();
    #pragma unroll
    for (int i=0;i<TT;i++) acc[i]=0.f;
    {
        const float4* w2v = (const float4*)W2 + tid*64;
        for (int m=0;m<64;m++){
            float4 w = w2v[m];
            #pragma unroll
            for (int i=0;i<TT;i++){
                float4 x = ((const float4*)pre1_s[i])[m];
                acc[i] += w.x*x.x + w.y*x.y + w.z*x.z + w.w*x.w;
            }
        }
    }
    float bv2 = b2[tid];
    #pragma unroll
    for (int i=0;i<TT;i++) g_pre2[(size_t)(t0+i)*(BB*HD) + b*HD + tid] = fmaxf(acc[i] + bv2, 0.f);
}

// ---------------- prologue 3: gpre[t][r][b] = Wih[:, :256] @ pre2[t] + bih + bhh ----
__global__ void __launch_bounds__(256) k_pregate(const float* __restrict__ Wih,
                                                 const float* __restrict__ bih,
                                                 const float* __restrict__ bhh){
    __shared__ float Xs[64][65];
    __shared__ float Ws[64][65];
    int tid = threadIdx.x;
    int n0 = blockIdx.x*64;
    int m0 = blockIdx.y*64;
    int tx = tid & 15, ty = tid >> 4;
    float acc[4][4];
    #pragma unroll
    for (int i=0;i<4;i++)
        #pragma unroll
        for (int j=0;j<4;j++) acc[i][j]=0.f;
    for (int k0=0;k0<256;k0+=64){
        for (int i=tid;i<64*64;i+=256){
            int mm=i>>6, kk=i&63;
            Xs[mm][kk] = g_pre2[(size_t)(m0+mm)*HD + k0+kk];
            Ws[mm][kk] = Wih[(size_t)(n0+mm)*512 + k0+kk];
        }
        __syncthreads();
        for (int k=0;k<64;k++){
            float xr[4], wr[4];
            #pragma unroll
            for (int i=0;i<4;i++){ xr[i]=Xs[ty*4+i][k]; wr[i]=Ws[tx*4+i][k]; }
            #pragma unroll
            for (int i=0;i<4;i++)
                #pragma unroll
                for (int j=0;j<4;j++) acc[i][j] = fmaf(xr[i], wr[j], acc[i][j]);
        }
        __syncthreads();
    }
    #pragma unroll
    for (int i=0;i<4;i++){
        int m = m0 + ty*4 + i; int t = m>>6, b = m&63;
        #pragma unroll
        for (int j=0;j<4;j++){
            int r = n0 + tx*4 + j;
            g_gpre[((size_t)t*1024 + r)*64 + b] = acc[i][j] + bih[r] + bhh[r];
        }
    }
}

// ---------------- prologue 4: init state, lengths, partial-zeroing, counters ----
__global__ void k_init(const float* __restrict__ bdec, const float* __restrict__ mask){
    __shared__ float red[256];
    int b = blockIdx.x, tid = threadIdx.x;
    g_h[0][b*HD+tid] = 0.f;
    g_q[b*AD+tid]    = bdec[tid];
    for (int i = b*256 + tid; i < 512*ED; i += 64*256) g_ctxp[i] = 0.f;
    if (tid < 8) g_sump[b*8 + tid] = 0.f;
    float s = 0.f;
    for (int i=tid;i<TE;i+=256) s += mask[b*TE+i];
    red[tid]=s; __syncthreads();
    for (int off=128; off; off>>=1){ if (tid<off) red[tid]+=red[tid+off]; __syncthreads(); }
    if (tid==0) g_len[b] = (int)(red[0] + 0.5f);
    if (b==0 && tid==0){ g_arrive = 0u; g_ticketA = 0u; }
}

// ---------------- fence-free grid barrier (release/acquire, no CCTL.IVALL) ------
__device__ __forceinline__ void gsync(unsigned &gen){
    __syncthreads();
    if (threadIdx.x == 0){
        gen += NCTA;
        unsigned* p = &g_arrive;
        asm volatile("red.release.gpu.add.u32 [%0], 1;" :: "l"(p) : "memory");
        unsigned v;
        do {
            asm volatile("ld.relaxed.gpu.u32 %0, [%1];" : "=r"(v) : "l"(p) : "memory");
        } while (v < gen);
        asm volatile("ld.acquire.gpu.u32 %0, [%1];" : "=r"(v) : "l"(p) : "memory");
    }
    __syncthreads();
}

// ---------------- persistent main kernel ----------------
struct SA { __half2 qh[AD]; float v[AD]; float ep[8][132]; float es[128]; float wctx[8][264]; };
struct SG { float x[8][516]; float rs[8]; float gsm[32][9]; };
struct SQ { float h[8][260]; };
union  SU { SA a; SG g; SQ q; };

__global__ void __launch_bounds__(256,2) k_main(
        const float* __restrict__ vw,  const float* __restrict__ vb,
        const float* __restrict__ Wih, const float* __restrict__ Whh,
        const float* __restrict__ Wdec, const float* __restrict__ bdec){
    __shared__ SU sm;
    __shared__ unsigned s_chunk;
    const int c   = blockIdx.x;
    const int tid = threadIdx.x;
    const int l   = tid & 31, w = tid >> 5;
    unsigned gen = 0;
    const float vb0 = vb[0];
    float c_state = 0.f;                      // cell state (valid in G-CTAs, tid<64)

    for (int t = 0; t < TO; t++){
        // ======== Phase A : attention — dynamic chunks (b, eighth of t) ========
        const unsigned baseA = (unsigned)t * 1024u;
        for (;;){
            if (tid == 0) s_chunk = atomicAdd(&g_ticketA, 1u);
            __syncthreads();                               // publish s_chunk
            const unsigned rel = s_chunk - baseA;          // uniform snapshot
            const bool done = (rel >= 512u);
            if (!done){
                const int b  = (int)(rel >> 3), e8 = (int)(rel & 7);
                const int t0 = e8 * 128;
                const int len = g_len[b];
                if (t0 < len){
                    {   // stage q (fp16 dup) + v (f32)
                        float qf = __ldcg(&g_q[b*AD + tid]);
                        sm.a.qh[tid] = __half2half2(__float2half(qf));
                        sm.a.v[tid]  = vw[tid];
                    }
                    __syncthreads();
                    // ---- energy: warp w owns a = w+8k; lane l owns t = t0+4l..+4 ----
                    float e4[4] = {0.f,0.f,0.f,0.f};
                    {
                        const uint2* ap = (const uint2*)g_attn_t
                                        + ((((size_t)(b*AD + w))*TE + t0) >> 2) + l;
                        const size_t astep = (size_t)8*(TE>>2);
                        #pragma unroll 4
                        for (int k = 0; k < 32; k++){
                            const int a = w + 8*k;
                            uint2 x = __ldcg(ap); ap += astep;
                            __half2 qa = sm.a.qh[a];
                            float  va = sm.a.v[a];
                            __half2 h0 = __hadd2(*(__half2*)&x.x, qa);
                            __half2 h1 = __hadd2(*(__half2*)&x.y, qa);
                            unsigned r0, r1;
                            asm("tanh.approx.f16x2 %0, %1;" : "=r"(r0) : "r"(*(unsigned*)&h0));
                            asm("tanh.approx.f16x2 %0, %1;" : "=r"(r1) : "r"(*(unsigned*)&h1));
                            float2 f0 = __half22float2(*(__half2*)&r0);
                            float2 f1 = __half22float2(*(__half2*)&r1);
                            e4[0] = fmaf(va, f0.x, e4[0]); e4[1] = fmaf(va, f0.y, e4[1]);
                            e4[2] = fmaf(va, f1.x, e4[2]); e4[3] = fmaf(va, f1.y, e4[3]);
                        }
                    }
                    #pragma unroll
                    for (int i=0;i<4;i++) sm.a.ep[w][l*4+i] = e4[i];
                    __syncthreads();
                    // ---- combine warps, exp, mask ----
                    if (tid < 128){
                        float s = 0.f;
                        #pragma unroll
                        for (int ww=0;ww<8;ww++) s += sm.a.ep[ww][tid];
                        sm.a.es[tid] = (t0 + tid < len) ? __expf(s + vb0) : 0.f;
                    }
                    __syncthreads();
                    if (tid < 32){
                        float s = sm.a.es[tid] + sm.a.es[tid+32] + sm.a.es[tid+64] + sm.a.es[tid+96];
                        #pragma unroll
                        for (int off=16; off; off>>=1) s += __shfl_xor_sync(0xffffffffu, s, off);
                        if (tid == 0) __stcg(&g_sump[b*8 + e8], s);
                    }
                    // ---- context: warp w owns t-sub [t0+w*16,+16), lane l owns d = 8l..+8 ----
                    float ca[8];
                    #pragma unroll
                    for (int i=0;i<8;i++) ca[i] = 0.f;
                    {
                        const int baset = t0 + w*16;
                        int iters = len - baset;
                        iters = iters < 0 ? 0 : (iters > 16 ? 16 : iters);
                        const uint4* ep4 = (const uint4*)g_enc_h + (((size_t)(b*TE + baset)) << 5) + l;
                        for (int i=0;i<iters;i++){
                            float ev = sm.a.es[w*16 + i];
                            uint4 x = __ldcg(ep4); ep4 += 32;
                            float2 f0 = __half22float2(*(__half2*)&x.x);
                            float2 f1 = __half22float2(*(__half2*)&x.y);
                            float2 f2 = __half22float2(*(__half2*)&x.z);
                            float2 f3 = __half22float2(*(__half2*)&x.w);
                            ca[0] = fmaf(ev, f0.x, ca[0]); ca[1] = fmaf(ev, f0.y, ca[1]);
                            ca[2] = fmaf(ev, f1.x, ca[2]); ca[3] = fmaf(ev, f1.y, ca[3]);
                            ca[4] = fmaf(ev, f2.x, ca[4]); ca[5] = fmaf(ev, f2.y, ca[5]);
                            ca[6] = fmaf(ev, f3.x, ca[6]); ca[7] = fmaf(ev, f3.y, ca[7]);
                        }
                    }
                    #pragma unroll
                    for (int j=0;j<8;j++) sm.a.wctx[w][l*8+j] = ca[j];
                    __syncthreads();
                    {
                        float s = 0.f;
                        #pragma unroll
                        for (int ww=0;ww<8;ww++) s += sm.a.wctx[ww][tid];
                        __stcg(&g_ctxp[(size_t)(b*8 + e8)*ED + tid], s);
                    }
                }
            }
            __syncthreads();                 // protect s_chunk + smem reuse on ALL paths
            if (done) break;
        }
        gsync(gen);
        if (c == 0 && tid == 0) atomicMax(&g_ticketA, (unsigned)(t+1) * 1024u);

        // ======== Phase G : gates + cell update (CTAs 0..255 : jblock x bblock) ========
        if (c < 256){
            const int jb = c >> 3;              // 32 j-blocks of 8
            const int b0 = (c & 7) * 8;         // 8 b-blocks of 8
            if (tid < 8){
                int b = b0 + tid;
                float ssum = 0.f;
                #pragma unroll
                for (int e=0;e<8;e++) ssum += __ldcg(&g_sump[b*8 + e]);
                sm.g.rs[tid] = __fdividef(1.f, ssum);
            }
            __syncthreads();
            const int ph = t & 1;
            for (int idx = tid; idx < 8*512; idx += 256){
                int bb = idx >> 9, k = idx & 511;
                int b = b0 + bb;
                float v;
                if (k < 256){
                    float s = 0.f;
                    #pragma unroll
                    for (int e=0;e<8;e++) s += __ldcg(&g_ctxp[(size_t)(b*8+e)*ED + k]);
                    v = s * sm.g.rs[bb];
                } else {
                    v = __ldcg(&g_h[ph][b*HD + (k - 256)]);
                }
                sm.g.x[bb][k] = v;
            }
            __syncthreads();
            // ctx history store (only j-block 0 CTAs own it)
            if (jb == 0){
                for (int idx = tid; idx < 8*256; idx += 256){
                    int bb = idx >> 8, k = idx & 255;
                    __stcg(&g_chist[(size_t)t*(BB*ED) + (b0+bb)*ED + k], sm.g.x[bb][k]);
                }
            }
            // GEMM: thread = (row rr = 4gates x 8j, bb)
            const int rr = tid >> 3, bb = tid & 7;
            const int r = (rr >> 3)*256 + jb*8 + (rr & 7);
            const int b = b0 + bb;
            float a0 = __ldcg(&g_gpre[((size_t)t*1024 + r)*64 + b]);
            float a1 = 0.f, a2 = 0.f, a3 = 0.f;
            const float4* w1 = (const float4*)Wih + (size_t)r*128 + 64;   // ctx cols
            const float4* w2 = (const float4*)Whh + (size_t)r*64;
            const float4* x1 = (const float4*)sm.g.x[bb];
            const float4* x2 = x1 + 64;
            #pragma unroll 4
            for (int k=0;k<64;k++){
                float4 ww = w1[k], xx = x1[k];
                a0 = fmaf(ww.x,xx.x,a0); a1 = fmaf(ww.y,xx.y,a1);
                a2 = fmaf(ww.z,xx.z,a2); a3 = fmaf(ww.w,xx.w,a3);
            }
            #pragma unroll 4
            for (int k=0;k<64;k++){
                float4 ww = w2[k], xx = x2[k];
                a0 = fmaf(ww.x,xx.x,a0); a1 = fmaf(ww.y,xx.y,a1);
                a2 = fmaf(ww.z,xx.z,a2); a3 = fmaf(ww.w,xx.w,a3);
            }
            sm.g.gsm[rr][bb] = (a0+a1) + (a2+a3);
            __syncthreads();
            if (tid < 64){
                const int jj = tid >> 3, bb2 = tid & 7;
                float gi = sm.g.gsm[ 0 + jj][bb2];
                float gf = sm.g.gsm[ 8 + jj][bb2];
                float gg = sm.g.gsm[16 + jj][bb2];
                float go = sm.g.gsm[24 + jj][bb2];
                float cn = sigm(gf)*c_state + sigm(gi)*tanh_acc(gg);
                float hn = sigm(go)*tanh_acc(cn);
                c_state = cn;
                const int b2 = b0 + bb2, j = jb*8 + jj;
                __stcg(&g_h[(t+1)&1][b2*HD + j], hn);
                __stcg(&g_hhist[(size_t)t*(BB*HD) + b2*HD + j], hn);
            }
        }
        gsync(gen);

        // ======== Phase Q : next query q = Wdec @ h_new + bdec (CTAs 0..255) ========
        if (c < 256){
            const int ra = c >> 3, b0 = (c & 7) * 8;
            const int ph1 = (t+1) & 1;
            for (int idx = tid; idx < 8*256; idx += 256)
                sm.q.h[idx >> 8][idx & 255] = __ldcg(&g_h[ph1][(b0 + (idx >> 8))*HD + (idx & 255)]);
            __syncthreads();
            if (tid < 64){
                const int ar = tid >> 3, bb = tid & 7;
                const int a = ra*8 + ar;
                float q0 = bdec[a], q1 = 0.f, q2 = 0.f, q3 = 0.f;
                const float4* wv = (const float4*)Wdec + (size_t)a*64;
                const float4* hv = (const float4*)sm.q.h[bb];
                #pragma unroll 8
                for (int k=0;k<64;k++){
                    float4 ww = wv[k], xx = hv[k];
                    q0 = fmaf(ww.x,xx.x,q0); q1 = fmaf(ww.y,xx.y,q1);
                    q2 = fmaf(ww.z,xx.z,q2); q3 = fmaf(ww.w,xx.w,q3);
                }
                __stcg(&g_q[(b0+bb)*AD + a], (q0+q1) + (q2+q3));
            }
            __syncthreads();
        }
        gsync(gen);
    }
}

// ---------------- epilogue: mel + stop heads from history ----------------
__global__ void __launch_bounds__(256) k_heads(const float* __restrict__ melW,
                                               const float* __restrict__ melb,
                                               const float* __restrict__ stopW,
                                               const float* __restrict__ stopb,
                                               float* __restrict__ out){
    __shared__ float comb[16][520];
    const int b = blockIdx.y, t0 = blockIdx.x * 16;
    const int tid = threadIdx.x;
    for (int idx = tid; idx < 16*256; idx += 256){
        int tt = idx >> 8, k = idx & 255;
        int t = t0 + tt;
        float hv = 0.f, cv = 0.f;
        if (t < TO){
            hv = g_hhist[(size_t)t*(BB*HD) + b*HD + k];
            cv = g_chist[(size_t)t*(BB*ED) + b*ED + k];
        }
        comb[tt][k] = hv; comb[tt][256+k] = cv;
    }
    __syncthreads();
    for (int idx = tid; idx < 16*81; idx += 256){
        int tt = idx / 81, n = idx - tt*81;
        int t = t0 + tt;
        if (t >= TO) continue;
        const float4* wv = (const float4*)((n < 80) ? (melW + n*512) : stopW);
        float a0 = (n < 80) ? melb[n] : stopb[0];
        float a1 = 0.f, a2 = 0.f, a3 = 0.f;
        const float4* cv = (const float4*)comb[tt];
        #pragma unroll 4
        for (int k=0;k<128;k++){
            float4 ww = wv[k], xx = cv[k];
            a0 = fmaf(ww.x,xx.x,a0); a1 = fmaf(ww.y,xx.y,a1);
            a2 = fmaf(ww.z,xx.z,a2); a3 = fmaf(ww.w,xx.w,a3);
        }
        float r = (a0+a1) + (a2+a3);
        if (n < 80) out[(b*TO + t)*NM + n] = r;
        else        out[(size_t)BB*TO*NM + b*TO + t] = r;
    }
}

// ---------------- launch ----------------
extern "C" void kernel_launch(void* const* d_in, const int* in_sizes, int n_in,
                              void* d_out, int out_size){
    (void)in_sizes; (void)n_in; (void)out_size;
    const float* enc  = (const float*)d_in[0];
    const float* tm   = (const float*)d_in[1];
    const float* Wenc = (const float*)d_in[2];
    const float* benc = (const float*)d_in[3];
    const float* Wdec = (const float*)d_in[4];
    const float* bdec = (const float*)d_in[5];
    const float* vw   = (const float*)d_in[6];
    const float* vb   = (const float*)d_in[7];
    const float* W1   = (const float*)d_in[8];
    const float* b1   = (const float*)d_in[9];
    const float* W2   = (const float*)d_in[10];
    const float* b2   = (const float*)d_in[11];
    const float* Wih  = (const float*)d_in[12];
    const float* Whh  = (const float*)d_in[13];
    const float* bih  = (const float*)d_in[14];
    const float* bhh  = (const float*)d_in[15];
    const float* melW = (const float*)d_in[16];
    const float* melb = (const float*)d_in[17];
    const float* stopW= (const float*)d_in[18];
    const float* stopb= (const float*)d_in[19];
    const float* mask = (const float*)d_in[20];
    float* out = (float*)d_out;

    k_prep_enc<<<dim3(64,64),256>>>(enc, Wenc, benc);
    k_prenet  <<<dim3(40,64),256>>>(tm, W1, b1, W2, b2);
    k_pregate <<<dim3(16,1000),256>>>(Wih, bih, bhh);
    k_init    <<<64,256>>>(bdec, mask);
    k_main    <<<NCTA,256>>>(vw, vb, Wih, Whh, Wdec, bdec);
    k_heads   <<<dim3(63,64),256>>>(melW, melb, stopW, stopb, out);
}